// round 6
// baseline (speedup 1.0000x reference)
#include <cuda_runtime.h>
#include <cstdint>

// EnhancedLDEPooling: B=16, T=2048, D=256, K=8
// K1: 256-thread blocks, cp.async-staged 16-row tiles.
//     Phase A: warp computes 2 rows' softmax weights (batched reduce-scatter).
//     Phase B: warp owns a (4k x 64dim) patch, sweeps all 16 rows from smem.
//     Per-lane accumulators: 16 u64 (no spills). No cross-warp merge needed.
// K2: chunk reduce (CH=8) + mean/var + LN(512).

#define BB 16
#define TT 2048
#define DD 256
#define KK 8
#define ROWS 256
#define CH (TT / ROWS)
#define TROWS 16
#define NTILE (ROWS / TROWS)
#define LOG2E 1.4426950408889634f
#define KREG 5

__device__ float g_wx [BB * CH * KK * DD];
__device__ float g_wx2[BB * CH * KK * DD];
__device__ float g_sw [BB * CH * KK];

typedef unsigned long long u64;

static __device__ __forceinline__ u64 pk2(float lo, float hi) {
    u64 r; asm("mov.b64 %0, {%1, %2};" : "=l"(r) : "f"(lo), "f"(hi)); return r;
}
static __device__ __forceinline__ void upk2(u64 v, float& a, float& b) {
    asm("mov.b64 {%0, %1}, %2;" : "=f"(a), "=f"(b) : "l"(v));
}
static __device__ __forceinline__ u64 ffma2(u64 a, u64 b, u64 c) {
    u64 d; asm("fma.rn.f32x2 %0, %1, %2, %3;" : "=l"(d) : "l"(a), "l"(b), "l"(c)); return d;
}
static __device__ __forceinline__ u64 fmul2(u64 a, u64 b) {
    u64 d; asm("mul.rn.f32x2 %0, %1, %2;" : "=l"(d) : "l"(a), "l"(b)); return d;
}
static __device__ __forceinline__ float ex2_fast(float v) {
    float r; asm("ex2.approx.f32 %0, %1;" : "=f"(r) : "f"(v)); return r;
}
static __device__ __forceinline__ uint32_t smem_u32(const void* p) {
    return (uint32_t)__cvta_generic_to_shared(p);
}
static __device__ __forceinline__ void cp16(uint32_t dst, const void* src) {
    asm volatile("cp.async.cg.shared.global [%0], [%1], 16;" :: "r"(dst), "l"(src));
}
static __device__ __forceinline__ void cp_commit() {
    asm volatile("cp.async.commit_group;");
}
static __device__ __forceinline__ void cp_wait1() {
    asm volatile("cp.async.wait_group 1;");
}

// 8-value reduce-scatter (prologue only): k = lane>>2
static __device__ __forceinline__ float rscat8(float r[8], int lane) {
    const bool t4 = (lane & 16) != 0, t3 = (lane & 8) != 0, t2 = (lane & 4) != 0;
#pragma unroll
    for (int i = 0; i < 4; i++) {
        float sel  = t4 ? r[i] : r[i + 4];
        float keep = t4 ? r[i + 4] : r[i];
        r[i] = keep + __shfl_xor_sync(0xffffffffu, sel, 16);
    }
#pragma unroll
    for (int i = 0; i < 2; i++) {
        float sel  = t3 ? r[i] : r[i + 2];
        float keep = t3 ? r[i + 2] : r[i];
        r[i] = keep + __shfl_xor_sync(0xffffffffu, sel, 8);
    }
    {
        float sel  = t2 ? r[0] : r[1];
        float keep = t2 ? r[1] : r[0];
        r[0] = keep + __shfl_xor_sync(0xffffffffu, sel, 4);
    }
    r[0] += __shfl_xor_sync(0xffffffffu, r[0], 2);
    r[0] += __shfl_xor_sync(0xffffffffu, r[0], 1);
    return r[0];
}

// 16-value (2 rows x 8 k) reduce-scatter: lane ends with full warp sum of
// v[r*8+k], k = lane>>2, r = (lane>>1)&1 (copies on bit0).
static __device__ __forceinline__ float rscat16(const float v[16], int lane) {
    const bool t4 = (lane & 16) != 0, t3 = (lane & 8) != 0;
    const bool t2 = (lane & 4) != 0,  t1 = (lane & 2) != 0;
    float u[8];
#pragma unroll
    for (int r = 0; r < 2; r++)
#pragma unroll
        for (int i = 0; i < 4; i++) {
            float sel  = t4 ? v[r * 8 + i] : v[r * 8 + i + 4];
            float keep = t4 ? v[r * 8 + i + 4] : v[r * 8 + i];
            u[r * 4 + i] = keep + __shfl_xor_sync(0xffffffffu, sel, 16);
        }
    float w2[4];
#pragma unroll
    for (int r = 0; r < 2; r++)
#pragma unroll
        for (int i = 0; i < 2; i++) {
            float sel  = t3 ? u[r * 4 + i] : u[r * 4 + i + 2];
            float keep = t3 ? u[r * 4 + i + 2] : u[r * 4 + i];
            w2[r * 2 + i] = keep + __shfl_xor_sync(0xffffffffu, sel, 8);
        }
    float y[2];
#pragma unroll
    for (int r = 0; r < 2; r++) {
        float sel  = t2 ? w2[r * 2] : w2[r * 2 + 1];
        float keep = t2 ? w2[r * 2 + 1] : w2[r * 2];
        y[r] = keep + __shfl_xor_sync(0xffffffffu, sel, 4);
    }
    float sel  = t1 ? y[0] : y[1];
    float keep = t1 ? y[1] : y[0];
    float z = keep + __shfl_xor_sync(0xffffffffu, sel, 2);
    z += __shfl_xor_sync(0xffffffffu, z, 1);
    return z;
}

__global__ __launch_bounds__(256, 1)
void lde_main(const float* __restrict__ x,
              const float* __restrict__ centers,
              const float* __restrict__ scale,
              const float* __restrict__ temperature)
{
    const int tid  = threadIdx.x;
    const int warp = tid >> 5;
    const int lane = tid & 31;
    const int b    = blockIdx.x >> 3;
    const int ch   = blockIdx.x & 7;
    const int K_id = lane >> 2;
    const int kg   = warp >> 2;      // k-group: k in [kg*4, kg*4+4)
    const int dg   = warp & 3;       // dim-group: dims [dg*64, dg*64+64)
    const int d0   = dg * 64 + lane * 2;

    __shared__ float sX[2][TROWS * DD];   // 32 KB staging
    __shared__ float sC[KK - KREG][DD];
    __shared__ float sW[TROWS][KK];       // per-tile weight table
    __shared__ float sSWb[8][KK];

    // ---- prologue: centers ----
    u64 cc[KREG][4];
    float c2p[KK];
    const float4* c4 = (const float4*)centers;
#pragma unroll
    for (int k = 0; k < KK; k++) {
        float4 a = __ldg(c4 + k * (DD / 4) + lane);
        float4 q = __ldg(c4 + k * (DD / 4) + 32 + lane);
        u64 p0 = pk2(a.x, a.y), p1 = pk2(a.z, a.w);
        u64 p2 = pk2(q.x, q.y), p3 = pk2(q.z, q.w);
        if (k < KREG) {
            cc[k][0] = p0; cc[k][1] = p1; cc[k][2] = p2; cc[k][3] = p3;
        } else if (warp == 0) {
            *(float4*)&sC[k - KREG][lane * 4]       = a;
            *(float4*)&sC[k - KREG][128 + lane * 4] = q;
        }
        u64 s = ffma2(p0, p0, ffma2(p1, p1, ffma2(p2, p2, fmul2(p3, p3))));
        float u, v; upk2(s, u, v);
        c2p[k] = u + v;
    }
    const float c2L  = rscat8(c2p, lane);
    const float tmp  = __ldg(temperature);
    const float a2L  = tmp * __ldg(scale + K_id) * LOG2E;
    const float ne2L = -a2L * c2L;

    // accumulators: 4 k's x 2 dims each (16 u64 total)
    u64 aw[4], aw2[4];
    float asw = 0.f;
#pragma unroll
    for (int k = 0; k < 4; k++) { aw[k] = 0ull; aw2[k] = 0ull; }

    const float4* xb4 = (const float4*)(x + (size_t)b * TT * DD) +
                        (size_t)(ch * ROWS) * (DD / 4);

    auto issue_tile = [&](int tt, int bf) {
        tt = tt < NTILE ? tt : NTILE - 1;
        const float4* src = xb4 + (size_t)tt * TROWS * (DD / 4);
        uint32_t dst = smem_u32(&sX[bf][0]);
#pragma unroll
        for (int j = 0; j < 4; j++) {
            int idx = j * 256 + tid;
            cp16(dst + idx * 16, src + idx);
        }
        cp_commit();
    };

    issue_tile(0, 0);
    cp_commit();

#pragma unroll 1
    for (int t = 0; t < NTILE; t++) {
        issue_tile(t + 1, (t + 1) & 1);
        cp_wait1();
        __syncthreads();

        const float* tb = &sX[t & 1][0];

        // ---- phase A: this warp computes weights for rows 2w, 2w+1 ----
        {
            const float4* row0 = (const float4*)(tb + (2 * warp) * DD);
            const float4* row1 = (const float4*)(tb + (2 * warp + 1) * DD);
            u64 xr[2][4];
            float4 a0 = row0[lane], q0 = row0[32 + lane];
            xr[0][0] = pk2(a0.x, a0.y); xr[0][1] = pk2(a0.z, a0.w);
            xr[0][2] = pk2(q0.x, q0.y); xr[0][3] = pk2(q0.z, q0.w);
            float4 a1 = row1[lane], q1 = row1[32 + lane];
            xr[1][0] = pk2(a1.x, a1.y); xr[1][1] = pk2(a1.z, a1.w);
            xr[1][2] = pk2(q1.x, q1.y); xr[1][3] = pk2(q1.z, q1.w);

            float v[16];
#pragma unroll
            for (int r = 0; r < 2; r++) {
                u64 s2 = ffma2(xr[r][0], xr[r][0], ffma2(xr[r][1], xr[r][1],
                         ffma2(xr[r][2], xr[r][2], fmul2(xr[r][3], xr[r][3]))));
                float t0, t1; upk2(s2, t0, t1);
                const float x2 = t0 + t1;
#pragma unroll
                for (int k = 0; k < KREG; k++) {
                    u64 s = ffma2(xr[r][0], cc[k][0], ffma2(xr[r][1], cc[k][1],
                            ffma2(xr[r][2], cc[k][2], fmul2(xr[r][3], cc[k][3]))));
                    float u, w; upk2(s, u, w);
                    v[r * 8 + k] = fmaf(2.f, u + w, -x2);
                }
#pragma unroll
                for (int k = KREG; k < KK; k++) {
                    const float4* sc = (const float4*)sC[k - KREG];
                    float4 a = sc[lane], q = sc[32 + lane];
                    u64 p0 = pk2(a.x, a.y), p1 = pk2(a.z, a.w);
                    u64 p2 = pk2(q.x, q.y), p3 = pk2(q.z, q.w);
                    u64 s = ffma2(xr[r][0], p0, ffma2(xr[r][1], p1,
                            ffma2(xr[r][2], p2, fmul2(xr[r][3], p3))));
                    float u, w; upk2(s, u, w);
                    v[r * 8 + k] = fmaf(2.f, u + w, -x2);
                }
            }

            const float rv    = rscat16(v, lane);
            const float logit = fmaf(a2L, rv, ne2L);
            float m = logit;
            m = fmaxf(m, __shfl_xor_sync(0xffffffffu, m, 4));
            m = fmaxf(m, __shfl_xor_sync(0xffffffffu, m, 8));
            m = fmaxf(m, __shfl_xor_sync(0xffffffffu, m, 16));
            const float e = ex2_fast(logit - m);
            float S = e;
            S += __shfl_xor_sync(0xffffffffu, S, 4);
            S += __shfl_xor_sync(0xffffffffu, S, 8);
            S += __shfl_xor_sync(0xffffffffu, S, 16);
            const float w = e * __fdividef(1.f, S);
            if ((lane & 1) == 0) {
                asw += w;
                sW[2 * warp + ((lane >> 1) & 1)][K_id] = w;
            }
        }
        __syncthreads();

        // ---- phase B: sweep 16 rows, accumulate own (4k x 2dim) patch ----
        const float2* xrow = (const float2*)(tb + d0);
        const float4* wrow = (const float4*)&sW[0][kg * 4];
#pragma unroll 4
        for (int r = 0; r < TROWS; r++) {
            float2 xv = xrow[r * (DD / 2)];
            float4 w4 = wrow[r * 2];             // sW[r][kg*4..+3] broadcast
            u64 xp = pk2(xv.x, xv.y);
            u64 xq = fmul2(xp, xp);
            u64 wp0 = pk2(w4.x, w4.x), wp1 = pk2(w4.y, w4.y);
            u64 wp2 = pk2(w4.z, w4.z), wp3 = pk2(w4.w, w4.w);
            aw[0]  = ffma2(wp0, xp, aw[0]);
            aw[1]  = ffma2(wp1, xp, aw[1]);
            aw[2]  = ffma2(wp2, xp, aw[2]);
            aw[3]  = ffma2(wp3, xp, aw[3]);
            aw2[0] = ffma2(wp0, xq, aw2[0]);
            aw2[1] = ffma2(wp1, xq, aw2[1]);
            aw2[2] = ffma2(wp2, xq, aw2[2]);
            aw2[3] = ffma2(wp3, xq, aw2[3]);
        }
        __syncthreads();   // protect sX buffer + sW before next tile
    }

    // sw totals (phase-A ownership: k = lane>>2, rows on bit1, zeros on bit0)
    asw += __shfl_xor_sync(0xffffffffu, asw, 1);
    asw += __shfl_xor_sync(0xffffffffu, asw, 2);
    if ((lane & 3) == 0) sSWb[warp][K_id] = asw;
    __syncthreads();

    // direct scratch write: warp owns (kg, dg) patch exclusively
    const int cbase = (b * CH + ch) * KK;
#pragma unroll
    for (int k = 0; k < 4; k++) {
        const int kglob = kg * 4 + k;
        float lo, hi;
        upk2(aw[k], lo, hi);
        *(float2*)(g_wx  + (size_t)(cbase + kglob) * DD + d0) = make_float2(lo, hi);
        upk2(aw2[k], lo, hi);
        *(float2*)(g_wx2 + (size_t)(cbase + kglob) * DD + d0) = make_float2(lo, hi);
    }
    if (tid < KK) {
        float s = 0.f;
#pragma unroll
        for (int wv = 0; wv < 8; wv++) s += sSWb[wv][tid];
        g_sw[(b * CH + ch) * KK + tid] = s;
    }
}

// ---- K2: chunk reduce (CH=8) + mean/var + LN(512) ----
__global__ __launch_bounds__(512)
void lde_finalize(const float* __restrict__ centers, float* __restrict__ out)
{
    const int b = blockIdx.x >> 3;
    const int k = blockIdx.x & 7;
    const int tid = threadIdx.x;

    __shared__ float sA[CH][DD];
    __shared__ float sB[CH][DD];
    __shared__ float sSum[2 * DD];
    __shared__ float sStat[2 * DD];
    __shared__ float sSwTot;
    __shared__ float red[16];

    {
        const int c = tid >> 6;
        const int g = tid & 63;
        const size_t base = ((size_t)(b * CH + c) * KK + k) * (DD / 4) + g;
        *(float4*)&sA[c][g * 4] = __ldg((const float4*)g_wx  + base);
        *(float4*)&sB[c][g * 4] = __ldg((const float4*)g_wx2 + base);
        if (tid == 0) {
            float s = 0.f;
#pragma unroll
            for (int c2 = 0; c2 < CH; c2++) s += g_sw[(b * CH + c2) * KK + k];
            sSwTot = s;
        }
    }
    __syncthreads();

    {
        const int half = tid >> 8;
        const int d = tid & 255;
        float s = 0.f;
        if (half == 0) {
#pragma unroll
            for (int c = 0; c < CH; c++) s += sA[c][d];
        } else {
#pragma unroll
            for (int c = 0; c < CH; c++) s += sB[c][d];
        }
        sSum[half * DD + d] = s;
    }
    __syncthreads();

    if (tid < DD) {
        const float sw   = sSwTot;
        const float swx  = sSum[tid];
        const float swx2 = sSum[DD + tid];
        const float cv   = __ldg(centers + k * DD + tid);
        const float mean = fmaf(-cv, sw, swx);
        const float E    = fmaf(cv * cv, sw, fmaf(-2.f * cv, swx, swx2));
        const float var  = fmaf(-mean, mean, E);
        sStat[tid]      = mean;
        sStat[DD + tid] = var;
    }
    __syncthreads();

    const float v0 = sStat[tid];
    float s = v0;
#pragma unroll
    for (int off = 16; off; off >>= 1) s += __shfl_xor_sync(0xffffffffu, s, off);
    if ((tid & 31) == 0) red[tid >> 5] = s;
    __syncthreads();
    float tot = 0.f;
#pragma unroll
    for (int i = 0; i < 16; i++) tot += red[i];
    const float mu = tot * (1.f / 512.f);
    __syncthreads();

    const float dm = v0 - mu;
    float sq = dm * dm;
#pragma unroll
    for (int off = 16; off; off >>= 1) sq += __shfl_xor_sync(0xffffffffu, sq, off);
    if ((tid & 31) == 0) red[tid >> 5] = sq;
    __syncthreads();
    float tot2 = 0.f;
#pragma unroll
    for (int i = 0; i < 16; i++) tot2 += red[i];
    const float rstd = rsqrtf(tot2 * (1.f / 512.f) + 1e-5f);

    out[(size_t)b * (KK * 2 * DD) + k * (2 * DD) + tid] = dm * rstd;
}

extern "C" void kernel_launch(void* const* d_in, const int* in_sizes, int n_in,
                              void* d_out, int out_size)
{
    const float* x = nullptr; const float* centers = nullptr;
    const float* scale = nullptr; const float* temperature = nullptr;
    for (int i = 0; i < n_in; i++) {
        switch (in_sizes[i]) {
            case BB * TT * DD: x = (const float*)d_in[i]; break;
            case KK * DD:      centers = (const float*)d_in[i]; break;
            case KK:           scale = (const float*)d_in[i]; break;
            case 1:            temperature = (const float*)d_in[i]; break;
        }
    }
    lde_main<<<BB * CH, 256>>>(x, centers, scale, temperature);
    lde_finalize<<<BB * KK, 512>>>(centers, (float*)d_out);
}

// round 9
// speedup vs baseline: 1.1238x; 1.1238x over previous
#include <cuda_runtime.h>
#include <cstdint>

// EnhancedLDEPooling: B=16, T=2048, D=256, K=8
// K1: 256-thread blocks, 2 CTAs/SM (occupancy!), cp.async-staged 16-row tiles.
//     Phase A: warp computes 2 rows' softmax weights (batched reduce-scatter).
//     Phase B: warp owns a (4k x 64dim) patch, sweeps 16 rows from smem.
// K2: chunk reduce (CH=16) + mean/var + LN(512).

#define BB 16
#define TT 2048
#define DD 256
#define KK 8
#define ROWS 128
#define CH (TT / ROWS)        // 16
#define TROWS 16
#define NTILE (ROWS / TROWS)  // 8
#define LOG2E 1.4426950408889634f
#define KREG 5

__device__ float g_wx [BB * CH * KK * DD];   // 2 MB
__device__ float g_wx2[BB * CH * KK * DD];   // 2 MB
__device__ float g_sw [BB * CH * KK];

typedef unsigned long long u64;

static __device__ __forceinline__ u64 pk2(float lo, float hi) {
    u64 r; asm("mov.b64 %0, {%1, %2};" : "=l"(r) : "f"(lo), "f"(hi)); return r;
}
static __device__ __forceinline__ void upk2(u64 v, float& a, float& b) {
    asm("mov.b64 {%0, %1}, %2;" : "=f"(a), "=f"(b) : "l"(v));
}
static __device__ __forceinline__ u64 ffma2(u64 a, u64 b, u64 c) {
    u64 d; asm("fma.rn.f32x2 %0, %1, %2, %3;" : "=l"(d) : "l"(a), "l"(b), "l"(c)); return d;
}
static __device__ __forceinline__ u64 fmul2(u64 a, u64 b) {
    u64 d; asm("mul.rn.f32x2 %0, %1, %2;" : "=l"(d) : "l"(a), "l"(b)); return d;
}
static __device__ __forceinline__ float ex2_fast(float v) {
    float r; asm("ex2.approx.f32 %0, %1;" : "=f"(r) : "f"(v)); return r;
}
static __device__ __forceinline__ uint32_t smem_u32(const void* p) {
    return (uint32_t)__cvta_generic_to_shared(p);
}
static __device__ __forceinline__ void cp16(uint32_t dst, const void* src) {
    asm volatile("cp.async.cg.shared.global [%0], [%1], 16;" :: "r"(dst), "l"(src));
}
static __device__ __forceinline__ void cp_commit() {
    asm volatile("cp.async.commit_group;");
}
static __device__ __forceinline__ void cp_wait1() {
    asm volatile("cp.async.wait_group 1;");
}

// 8-value reduce-scatter (prologue only): k = lane>>2
static __device__ __forceinline__ float rscat8(float r[8], int lane) {
    const bool t4 = (lane & 16) != 0, t3 = (lane & 8) != 0, t2 = (lane & 4) != 0;
#pragma unroll
    for (int i = 0; i < 4; i++) {
        float sel  = t4 ? r[i] : r[i + 4];
        float keep = t4 ? r[i + 4] : r[i];
        r[i] = keep + __shfl_xor_sync(0xffffffffu, sel, 16);
    }
#pragma unroll
    for (int i = 0; i < 2; i++) {
        float sel  = t3 ? r[i] : r[i + 2];
        float keep = t3 ? r[i + 2] : r[i];
        r[i] = keep + __shfl_xor_sync(0xffffffffu, sel, 8);
    }
    {
        float sel  = t2 ? r[0] : r[1];
        float keep = t2 ? r[1] : r[0];
        r[0] = keep + __shfl_xor_sync(0xffffffffu, sel, 4);
    }
    r[0] += __shfl_xor_sync(0xffffffffu, r[0], 2);
    r[0] += __shfl_xor_sync(0xffffffffu, r[0], 1);
    return r[0];
}

// 16-value (2 rows x 8 k) reduce-scatter: lane ends with full warp sum of
// v[r*8+k], k = lane>>2, r = (lane>>1)&1 (copies on bit0).
static __device__ __forceinline__ float rscat16(const float v[16], int lane) {
    const bool t4 = (lane & 16) != 0, t3 = (lane & 8) != 0;
    const bool t2 = (lane & 4) != 0,  t1 = (lane & 2) != 0;
    float u[8];
#pragma unroll
    for (int r = 0; r < 2; r++)
#pragma unroll
        for (int i = 0; i < 4; i++) {
            float sel  = t4 ? v[r * 8 + i] : v[r * 8 + i + 4];
            float keep = t4 ? v[r * 8 + i + 4] : v[r * 8 + i];
            u[r * 4 + i] = keep + __shfl_xor_sync(0xffffffffu, sel, 16);
        }
    float w2[4];
#pragma unroll
    for (int r = 0; r < 2; r++)
#pragma unroll
        for (int i = 0; i < 2; i++) {
            float sel  = t3 ? u[r * 4 + i] : u[r * 4 + i + 2];
            float keep = t3 ? u[r * 4 + i + 2] : u[r * 4 + i];
            w2[r * 2 + i] = keep + __shfl_xor_sync(0xffffffffu, sel, 8);
        }
    float y[2];
#pragma unroll
    for (int r = 0; r < 2; r++) {
        float sel  = t2 ? w2[r * 2] : w2[r * 2 + 1];
        float keep = t2 ? w2[r * 2 + 1] : w2[r * 2];
        y[r] = keep + __shfl_xor_sync(0xffffffffu, sel, 4);
    }
    float sel  = t1 ? y[0] : y[1];
    float keep = t1 ? y[1] : y[0];
    float z = keep + __shfl_xor_sync(0xffffffffu, sel, 2);
    z += __shfl_xor_sync(0xffffffffu, z, 1);
    return z;
}

__global__ __launch_bounds__(256, 2)
void lde_main(const float* __restrict__ x,
              const float* __restrict__ centers,
              const float* __restrict__ scale,
              const float* __restrict__ temperature)
{
    const int tid  = threadIdx.x;
    const int warp = tid >> 5;
    const int lane = tid & 31;
    const int b    = blockIdx.x >> 4;
    const int ch   = blockIdx.x & 15;
    const int K_id = lane >> 2;
    const int kg   = warp >> 2;      // k-group: k in [kg*4, kg*4+4)
    const int dg   = warp & 3;       // dim-group: dims [dg*64, dg*64+64)
    const int d0   = dg * 64 + lane * 2;

    __shared__ float sX[2][TROWS * DD];   // 32 KB staging
    __shared__ float sC[KK - KREG][DD];
    __shared__ float sW[TROWS][KK];       // per-tile weight table
    __shared__ float sSWb[8][KK];

    // ---- prologue: centers ----
    u64 cc[KREG][4];
    float c2p[KK];
    const float4* c4 = (const float4*)centers;
#pragma unroll
    for (int k = 0; k < KK; k++) {
        float4 a = __ldg(c4 + k * (DD / 4) + lane);
        float4 q = __ldg(c4 + k * (DD / 4) + 32 + lane);
        u64 p0 = pk2(a.x, a.y), p1 = pk2(a.z, a.w);
        u64 p2 = pk2(q.x, q.y), p3 = pk2(q.z, q.w);
        if (k < KREG) {
            cc[k][0] = p0; cc[k][1] = p1; cc[k][2] = p2; cc[k][3] = p3;
        } else if (warp == 0) {
            *(float4*)&sC[k - KREG][lane * 4]       = a;
            *(float4*)&sC[k - KREG][128 + lane * 4] = q;
        }
        u64 s = ffma2(p0, p0, ffma2(p1, p1, ffma2(p2, p2, fmul2(p3, p3))));
        float u, v; upk2(s, u, v);
        c2p[k] = u + v;
    }
    const float c2L  = rscat8(c2p, lane);
    const float tmp  = __ldg(temperature);
    const float a2L  = tmp * __ldg(scale + K_id) * LOG2E;
    const float ne2L = -a2L * c2L;

    // accumulators: 4 k's x 2 dims each
    u64 aw[4], aw2[4];
    float asw = 0.f;
#pragma unroll
    for (int k = 0; k < 4; k++) { aw[k] = 0ull; aw2[k] = 0ull; }

    const float4* xb4 = (const float4*)(x + (size_t)b * TT * DD) +
                        (size_t)(ch * ROWS) * (DD / 4);

    auto issue_tile = [&](int tt, int bf) {
        tt = tt < NTILE ? tt : NTILE - 1;
        const float4* src = xb4 + (size_t)tt * TROWS * (DD / 4);
        uint32_t dst = smem_u32(&sX[bf][0]);
#pragma unroll
        for (int j = 0; j < 4; j++) {
            int idx = j * 256 + tid;
            cp16(dst + idx * 16, src + idx);
        }
        cp_commit();
    };

    issue_tile(0, 0);
    cp_commit();

#pragma unroll 1
    for (int t = 0; t < NTILE; t++) {
        issue_tile(t + 1, (t + 1) & 1);
        cp_wait1();
        __syncthreads();

        const float* tb = &sX[t & 1][0];

        // ---- phase A: this warp computes weights for rows 2w, 2w+1 ----
        {
            const float4* row0 = (const float4*)(tb + (2 * warp) * DD);
            const float4* row1 = (const float4*)(tb + (2 * warp + 1) * DD);
            u64 xr[2][4];
            float4 a0 = row0[lane], q0 = row0[32 + lane];
            xr[0][0] = pk2(a0.x, a0.y); xr[0][1] = pk2(a0.z, a0.w);
            xr[0][2] = pk2(q0.x, q0.y); xr[0][3] = pk2(q0.z, q0.w);
            float4 a1 = row1[lane], q1 = row1[32 + lane];
            xr[1][0] = pk2(a1.x, a1.y); xr[1][1] = pk2(a1.z, a1.w);
            xr[1][2] = pk2(q1.x, q1.y); xr[1][3] = pk2(q1.z, q1.w);

            float v[16];
#pragma unroll
            for (int r = 0; r < 2; r++) {
                u64 s2 = ffma2(xr[r][0], xr[r][0], ffma2(xr[r][1], xr[r][1],
                         ffma2(xr[r][2], xr[r][2], fmul2(xr[r][3], xr[r][3]))));
                float t0, t1; upk2(s2, t0, t1);
                const float x2 = t0 + t1;
#pragma unroll
                for (int k = 0; k < KREG; k++) {
                    u64 s = ffma2(xr[r][0], cc[k][0], ffma2(xr[r][1], cc[k][1],
                            ffma2(xr[r][2], cc[k][2], fmul2(xr[r][3], cc[k][3]))));
                    float u, w; upk2(s, u, w);
                    v[r * 8 + k] = fmaf(2.f, u + w, -x2);
                }
#pragma unroll
                for (int k = KREG; k < KK; k++) {
                    const float4* sc = (const float4*)sC[k - KREG];
                    float4 a = sc[lane], q = sc[32 + lane];
                    u64 p0 = pk2(a.x, a.y), p1 = pk2(a.z, a.w);
                    u64 p2 = pk2(q.x, q.y), p3 = pk2(q.z, q.w);
                    u64 s = ffma2(xr[r][0], p0, ffma2(xr[r][1], p1,
                            ffma2(xr[r][2], p2, fmul2(xr[r][3], p3))));
                    float u, w; upk2(s, u, w);
                    v[r * 8 + k] = fmaf(2.f, u + w, -x2);
                }
            }

            const float rv    = rscat16(v, lane);
            const float logit = fmaf(a2L, rv, ne2L);
            float m = logit;
            m = fmaxf(m, __shfl_xor_sync(0xffffffffu, m, 4));
            m = fmaxf(m, __shfl_xor_sync(0xffffffffu, m, 8));
            m = fmaxf(m, __shfl_xor_sync(0xffffffffu, m, 16));
            const float e = ex2_fast(logit - m);
            float S = e;
            S += __shfl_xor_sync(0xffffffffu, S, 4);
            S += __shfl_xor_sync(0xffffffffu, S, 8);
            S += __shfl_xor_sync(0xffffffffu, S, 16);
            const float w = e * __fdividef(1.f, S);
            if ((lane & 1) == 0) {
                asw += w;
                sW[2 * warp + ((lane >> 1) & 1)][K_id] = w;
            }
        }
        __syncthreads();

        // ---- phase B: sweep 16 rows, accumulate own (4k x 2dim) patch ----
        const float2* xrow = (const float2*)(tb + d0);
        const float4* wrow = (const float4*)&sW[0][kg * 4];
#pragma unroll 4
        for (int r = 0; r < TROWS; r++) {
            float2 xv = xrow[r * (DD / 2)];
            float4 w4 = wrow[r * 2];             // sW[r][kg*4..+3] broadcast
            u64 xp = pk2(xv.x, xv.y);
            u64 xq = fmul2(xp, xp);
            u64 wp0 = pk2(w4.x, w4.x), wp1 = pk2(w4.y, w4.y);
            u64 wp2 = pk2(w4.z, w4.z), wp3 = pk2(w4.w, w4.w);
            aw[0]  = ffma2(wp0, xp, aw[0]);
            aw[1]  = ffma2(wp1, xp, aw[1]);
            aw[2]  = ffma2(wp2, xp, aw[2]);
            aw[3]  = ffma2(wp3, xp, aw[3]);
            aw2[0] = ffma2(wp0, xq, aw2[0]);
            aw2[1] = ffma2(wp1, xq, aw2[1]);
            aw2[2] = ffma2(wp2, xq, aw2[2]);
            aw2[3] = ffma2(wp3, xq, aw2[3]);
        }
        __syncthreads();   // protect sX buffer + sW before next tile
    }

    // sw totals (phase-A ownership: k = lane>>2, rows on bit1, zeros on bit0)
    asw += __shfl_xor_sync(0xffffffffu, asw, 1);
    asw += __shfl_xor_sync(0xffffffffu, asw, 2);
    if ((lane & 3) == 0) sSWb[warp][K_id] = asw;
    __syncthreads();

    // direct scratch write: warp owns (kg, dg) patch exclusively
    const int cbase = (b * CH + ch) * KK;
#pragma unroll
    for (int k = 0; k < 4; k++) {
        const int kglob = kg * 4 + k;
        float lo, hi;
        upk2(aw[k], lo, hi);
        *(float2*)(g_wx  + (size_t)(cbase + kglob) * DD + d0) = make_float2(lo, hi);
        upk2(aw2[k], lo, hi);
        *(float2*)(g_wx2 + (size_t)(cbase + kglob) * DD + d0) = make_float2(lo, hi);
    }
    if (tid < KK) {
        float s = 0.f;
#pragma unroll
        for (int wv = 0; wv < 8; wv++) s += sSWb[wv][tid];
        g_sw[(b * CH + ch) * KK + tid] = s;
    }
}

// ---- K2: chunk reduce (CH=16) + mean/var + LN(512) ----
__global__ __launch_bounds__(512)
void lde_finalize(const float* __restrict__ centers, float* __restrict__ out)
{
    const int b = blockIdx.x >> 3;
    const int k = blockIdx.x & 7;
    const int tid = threadIdx.x;

    __shared__ float sA[CH][DD];     // 16 KB
    __shared__ float sB[CH][DD];     // 16 KB
    __shared__ float sSum[2 * DD];
    __shared__ float sStat[2 * DD];
    __shared__ float sSwTot;
    __shared__ float red[16];

    {
        const int c = tid >> 5;          // chunk 0..15
        const int s = tid & 31;
        const size_t base = ((size_t)(b * CH + c) * KK + k) * (DD / 4);
        const float4* gw  = (const float4*)g_wx;
        const float4* gw2 = (const float4*)g_wx2;
        float4 v0 = __ldg(gw  + base + s);
        float4 v1 = __ldg(gw  + base + s + 32);
        float4 v2 = __ldg(gw2 + base + s);
        float4 v3 = __ldg(gw2 + base + s + 32);
        *(float4*)&sA[c][s * 4]        = v0;
        *(float4*)&sA[c][(s + 32) * 4] = v1;
        *(float4*)&sB[c][s * 4]        = v2;
        *(float4*)&sB[c][(s + 32) * 4] = v3;
        if (tid == 0) {
            float t = 0.f;
#pragma unroll
            for (int c2 = 0; c2 < CH; c2++) t += g_sw[(b * CH + c2) * KK + k];
            sSwTot = t;
        }
    }
    __syncthreads();

    {
        const int half = tid >> 8;
        const int d = tid & 255;
        float s = 0.f;
        if (half == 0) {
#pragma unroll
            for (int c = 0; c < CH; c++) s += sA[c][d];
        } else {
#pragma unroll
            for (int c = 0; c < CH; c++) s += sB[c][d];
        }
        sSum[half * DD + d] = s;
    }
    __syncthreads();

    if (tid < DD) {
        const float sw   = sSwTot;
        const float swx  = sSum[tid];
        const float swx2 = sSum[DD + tid];
        const float cv   = __ldg(centers + k * DD + tid);
        const float mean = fmaf(-cv, sw, swx);
        const float E    = fmaf(cv * cv, sw, fmaf(-2.f * cv, swx, swx2));
        const float var  = fmaf(-mean, mean, E);
        sStat[tid]      = mean;
        sStat[DD + tid] = var;
    }
    __syncthreads();

    const float v0 = sStat[tid];
    float s = v0;
#pragma unroll
    for (int off = 16; off; off >>= 1) s += __shfl_xor_sync(0xffffffffu, s, off);
    if ((tid & 31) == 0) red[tid >> 5] = s;
    __syncthreads();
    float tot = 0.f;
#pragma unroll
    for (int i = 0; i < 16; i++) tot += red[i];
    const float mu = tot * (1.f / 512.f);
    __syncthreads();

    const float dm = v0 - mu;
    float sq = dm * dm;
#pragma unroll
    for (int off = 16; off; off >>= 1) sq += __shfl_xor_sync(0xffffffffu, sq, off);
    if ((tid & 31) == 0) red[tid >> 5] = sq;
    __syncthreads();
    float tot2 = 0.f;
#pragma unroll
    for (int i = 0; i < 16; i++) tot2 += red[i];
    const float rstd = rsqrtf(tot2 * (1.f / 512.f) + 1e-5f);

    out[(size_t)b * (KK * 2 * DD) + k * (2 * DD) + tid] = dm * rstd;
}

extern "C" void kernel_launch(void* const* d_in, const int* in_sizes, int n_in,
                              void* d_out, int out_size)
{
    const float* x = nullptr; const float* centers = nullptr;
    const float* scale = nullptr; const float* temperature = nullptr;
    for (int i = 0; i < n_in; i++) {
        switch (in_sizes[i]) {
            case BB * TT * DD: x = (const float*)d_in[i]; break;
            case KK * DD:      centers = (const float*)d_in[i]; break;
            case KK:           scale = (const float*)d_in[i]; break;
            case 1:            temperature = (const float*)d_in[i]; break;
        }
    }
    lde_main<<<BB * CH, 256>>>(x, centers, scale, temperature);
    lde_finalize<<<BB * KK, 512>>>(centers, (float*)d_out);
}